// round 3
// baseline (speedup 1.0000x reference)
#include <cuda_runtime.h>

#define NSTEPS 50
#define LRATE  0.1f
#define BMAX   8192

__device__ float g_c0[BMAX];

typedef unsigned long long u64;

__device__ __forceinline__ u64 pk2(float lo, float hi) {
    u64 r; asm("mov.b64 %0, {%1,%2};" : "=l"(r) : "f"(lo), "f"(hi)); return r;
}
__device__ __forceinline__ void upk2(u64 v, float& lo, float& hi) {
    asm("mov.b64 {%0,%1}, %2;" : "=f"(lo), "=f"(hi) : "l"(v));
}
__device__ __forceinline__ void fma2(u64& d, u64 a, u64 b) {
    asm("fma.rn.f32x2 %0, %1, %2, %0;" : "+l"(d) : "l"(a), "l"(b));
}

// ---------------------------------------------------------------------------
// Kernel 1: 1-D nearest neighbor (|ci-cj| == sqrt((ci-cj)^2) exactly in RN).
// ---------------------------------------------------------------------------
#define NN_TILE 2048
__global__ __launch_bounds__(256) void nn_kernel(const float* __restrict__ c, int B) {
    __shared__ float ct[NN_TILE];
    int lane = threadIdx.x & 31;
    int w    = threadIdx.x >> 5;
    int q    = blockIdx.x * 8 + w;
    float cq = (q < B) ? c[q] : 0.f;
    float bestD = 3.0e38f; int bestJ = 0;
    for (int t0 = 0; t0 < B; t0 += NN_TILE) {
        int nt = min(NN_TILE, B - t0);
        __syncthreads();
        for (int i = threadIdx.x; i < nt; i += 256) ct[i] = c[t0 + i];
        __syncthreads();
        for (int jj = lane; jj < nt; jj += 32) {
            int j = t0 + jj;
            float d = fabsf(cq - ct[jj]);
            if (j == q) d += 1e9f;
            if (d < bestD) { bestD = d; bestJ = j; }
        }
    }
#pragma unroll
    for (int off = 16; off; off >>= 1) {
        float dO = __shfl_down_sync(0xffffffffu, bestD, off);
        int   jO = __shfl_down_sync(0xffffffffu, bestJ, off);
        if (dO < bestD || (dO == bestD && jO < bestJ)) { bestD = dO; bestJ = jO; }
    }
    if (lane == 0 && q < B) g_c0[q] = c[bestJ];
}

// ---------------------------------------------------------------------------
// Kernel 2 helpers
// ---------------------------------------------------------------------------
// One 64x(8n x 2s) tile-matvec: acc[2p+e] accumulates neuron pair (n0+2p, n0+2p+1)
// for sample e. Weights in layout W[k][n] at Wbase (row stride 64 floats);
// activations as duplicated {v,v} u64 at act[k*8 + sT2 + e].
__device__ __forceinline__ void matvec(const float* __restrict__ Wbase,
                                       const u64* __restrict__ act,
                                       int n0, int sT2, u64 acc[8]) {
#pragma unroll 8
    for (int k = 0; k < 64; k++) {
        const float* wp = Wbase + k * 64 + n0;
        ulonglong2 w01 = *(const ulonglong2*)(wp);
        ulonglong2 w23 = *(const ulonglong2*)(wp + 4);
        ulonglong2 h   = *(const ulonglong2*)(act + k * 8 + sT2);
        fma2(acc[0], w01.x, h.x); fma2(acc[1], w01.x, h.y);
        fma2(acc[2], w01.y, h.x); fma2(acc[3], w01.y, h.y);
        fma2(acc[4], w23.x, h.x); fma2(acc[5], w23.x, h.y);
        fma2(acc[6], w23.y, h.x); fma2(acc[7], w23.y, h.y);
    }
}

// acc[8] -> z[16] with z[e*8 + r] = value for neuron n0+r, sample e
__device__ __forceinline__ void unpack16(const u64 acc[8], float z[16]) {
    upk2(acc[0], z[0], z[1]); upk2(acc[1], z[8],  z[9]);
    upk2(acc[2], z[2], z[3]); upk2(acc[3], z[10], z[11]);
    upk2(acc[4], z[4], z[5]); upk2(acc[5], z[12], z[13]);
    upk2(acc[6], z[6], z[7]); upk2(acc[7], z[14], z[15]);
}

// store v[e*8+r] duplicated {v,v} into buf[(n0+r)*8 + sT2 + e]
__device__ __forceinline__ void store_dup(u64* __restrict__ buf, int n0, int sT2,
                                          const float v[16]) {
#pragma unroll
    for (int r = 0; r < 8; r++) {
        ulonglong2 t;
        t.x = pk2(v[r],     v[r]);
        t.y = pk2(v[8 + r], v[8 + r]);
        *(ulonglong2*)(buf + (n0 + r) * 8 + sT2) = t;
    }
}

// ---------------------------------------------------------------------------
// Kernel 2: block = 128 threads = 4 warps; each warp privately owns 8 samples.
// Lane: nT = lane&7 (neuron tile, 8 neurons each), sT = lane>>3 (2 samples).
// Weights shared block-wide (both orientations); activations warp-private;
// y in registers; gy via shfl_xor butterfly; only __syncwarp in the hot loop.
// ---------------------------------------------------------------------------
__global__ __launch_bounds__(128, 2) void solver_kernel(
    const float* __restrict__ x,
    const float* __restrict__ W1, const float* __restrict__ b1,
    const float* __restrict__ W2, const float* __restrict__ b2,
    const float* __restrict__ W3, const float* __restrict__ b3,
    const float* __restrict__ W4,
    float* __restrict__ out)
{
    extern __shared__ __align__(16) char smraw[];
    float* W2T = (float*)smraw;          // [64][64]  W2T[k][n] = W2[n][k]
    float* W3T = W2T + 4096;             // [64][64]
    float* W2N = W3T + 4096;             // [64][64]  natural
    float* W3N = W2N + 4096;             // [64][64]
    u64*  Acts = (u64*)(W3N + 4096);     // 4 warps x 2 buffers x [64][8]

    int tid  = threadIdx.x;
    int lane = tid & 31;
    int warp = tid >> 5;
    int nT = lane & 7, sT = lane >> 3;
    int n0 = nT * 8;
    int sT2 = sT * 2;

    // load natural weights (coalesced float4)
    for (int i = tid; i < 1024; i += 128) {
        ((float4*)W2N)[i] = ((const float4*)W2)[i];
        ((float4*)W3N)[i] = ((const float4*)W3)[i];
    }
    __syncthreads();
    // transposes (one-time; conflict cost negligible)
    for (int i = tid; i < 4096; i += 128) {
        int n = i >> 6, k = i & 63;
        W2T[k * 64 + n] = W2N[i];
        W3T[k * 64 + n] = W3N[i];
    }

    u64* myA = Acts + warp * 1024;       // [64][8] dup pairs (h1 / g3)
    u64* myB = myA + 512;                // [64][8] dup pairs (h2 / g2)

    int gs = blockIdx.x * 32 + warp * 8 + sT2;   // this thread's 2 samples
    float xs0 = x[gs], xs1 = x[gs + 1];
    float c00 = g_c0[gs], c01 = g_c0[gs + 1];

    // per-neuron layer-1 constants: a[e*8+r] = W1x*x + W1c*c0 + b1
    float a[16], w1y[8];
#pragma unroll
    for (int r = 0; r < 8; r++) {
        int n = n0 + r;
        float w1x = W1[n * 3 + 0]; w1y[r] = W1[n * 3 + 1];
        float w1c = W1[n * 3 + 2]; float bb = b1[n];
        a[r]     = fmaf(w1x, xs0, fmaf(w1c, c00, bb));
        a[8 + r] = fmaf(w1x, xs1, fmaf(w1c, c01, bb));
    }
    u64 bp2[4], bp3[4];
    float w4r[8];
#pragma unroll
    for (int p = 0; p < 4; p++) {
        bp2[p] = pk2(b2[n0 + 2 * p], b2[n0 + 2 * p + 1]);
        bp3[p] = pk2(b3[n0 + 2 * p], b3[n0 + 2 * p + 1]);
    }
#pragma unroll
    for (int r = 0; r < 8; r++) w4r[r] = W4[n0 + r];
    __syncthreads();

    float y0 = 0.f, y1 = 0.f;            // Y_MEAN = 0

    for (int step = 0; step < NSTEPS; step++) {
        // ---- layer 1 (rank-1 in y) ----
        float z1[16], h1[16];
#pragma unroll
        for (int r = 0; r < 8; r++) {
            z1[r]     = fmaf(w1y[r], y0, a[r]);
            z1[8 + r] = fmaf(w1y[r], y1, a[8 + r]);
            h1[r]     = fmaxf(z1[r], 0.f);
            h1[8 + r] = fmaxf(z1[8 + r], 0.f);
        }
        store_dup(myA, n0, sT2, h1);
        __syncwarp();

        // ---- fwd2: z2 = W2 h1 + b2 ----
        u64 acc[8];
#pragma unroll
        for (int p = 0; p < 4; p++) { acc[2 * p] = bp2[p]; acc[2 * p + 1] = bp2[p]; }
        matvec(W2T, myA, n0, sT2, acc);
        float z2[16], h2[16];
        unpack16(acc, z2);
#pragma unroll
        for (int e = 0; e < 16; e++) h2[e] = fmaxf(z2[e], 0.f);
        store_dup(myB, n0, sT2, h2);
        __syncwarp();

        // ---- fwd3: z3 = W3 h2 + b3 -> g3 = (z3>0)*W4 ----
#pragma unroll
        for (int p = 0; p < 4; p++) { acc[2 * p] = bp3[p]; acc[2 * p + 1] = bp3[p]; }
        matvec(W3T, myB, n0, sT2, acc);
        float z3[16], g3[16];
        unpack16(acc, z3);
#pragma unroll
        for (int e = 0; e < 16; e++) g3[e] = (z3[e] > 0.f) ? w4r[e & 7] : 0.f;
        store_dup(myA, n0, sT2, g3);
        __syncwarp();

        // ---- bwd3: g2 = (z2>0) .* (W3^T g3) ----
#pragma unroll
        for (int p = 0; p < 8; p++) acc[p] = 0;
        matvec(W3N, myA, n0, sT2, acc);
        float s2[16], g2[16];
        unpack16(acc, s2);
#pragma unroll
        for (int e = 0; e < 16; e++) g2[e] = (z2[e] > 0.f) ? s2[e] : 0.f;
        store_dup(myB, n0, sT2, g2);
        __syncwarp();

        // ---- bwd2: g1 = (z1>0) .* (W2^T g2);  gy = sum_n w1y[n] g1[n] ----
#pragma unroll
        for (int p = 0; p < 8; p++) acc[p] = 0;
        matvec(W2N, myB, n0, sT2, acc);
        float s1[16];
        unpack16(acc, s1);
        float pg0 = 0.f, pg1 = 0.f;
#pragma unroll
        for (int r = 0; r < 8; r++) {
            float ga = (z1[r]     > 0.f) ? s1[r]     : 0.f;
            float gb = (z1[8 + r] > 0.f) ? s1[8 + r] : 0.f;
            pg0 = fmaf(w1y[r], ga, pg0);
            pg1 = fmaf(w1y[r], gb, pg1);
        }
        // butterfly over the 8 neuron-lanes (xor bits 0..2): all lanes get sum
#pragma unroll
        for (int off = 1; off < 8; off <<= 1) {
            pg0 += __shfl_xor_sync(0xffffffffu, pg0, off);
            pg1 += __shfl_xor_sync(0xffffffffu, pg1, off);
        }
        y0 -= LRATE * pg0;
        y1 -= LRATE * pg1;
        __syncwarp();
    }

    if (nT == 0) { out[gs] = y0; out[gs + 1] = y1; }
}

// ---------------------------------------------------------------------------
// Launch
// ---------------------------------------------------------------------------
extern "C" void kernel_launch(void* const* d_in, const int* in_sizes, int n_in,
                              void* d_out, int out_size) {
    const float* x  = (const float*)d_in[0];
    const float* c  = (const float*)d_in[1];
    const float* W1 = (const float*)d_in[2];
    const float* b1 = (const float*)d_in[3];
    const float* W2 = (const float*)d_in[4];
    const float* b2 = (const float*)d_in[5];
    const float* W3 = (const float*)d_in[6];
    const float* b3 = (const float*)d_in[7];
    const float* W4 = (const float*)d_in[8];
    // d_in[9] = b4: constant offset, no effect on dE/dy
    float* out = (float*)d_out;
    int B = in_sizes[0];

    // smem: 4 x 4096 floats (weights) + 4096 u64 (acts) = 65536 + 32768 = 98304 B
    const int SMEM = 4 * 4096 * 4 + 4096 * 8;
    cudaFuncSetAttribute(solver_kernel,
                         cudaFuncAttributeMaxDynamicSharedMemorySize, SMEM);

    nn_kernel<<<(B + 7) / 8, 256>>>(c, B);
    solver_kernel<<<B / 32, 128, SMEM>>>(x, W1, b1, W2, b2, W3, b3, W4, out);
}

// round 4
// speedup vs baseline: 2.5189x; 2.5189x over previous
#include <cuda_runtime.h>

#define NSTEPS 50
#define LRATE  0.1f
#define BMAX   8192

__device__ float g_c0[BMAX];

typedef unsigned long long u64;

__device__ __forceinline__ u64 pk2(float lo, float hi) {
    u64 r; asm("mov.b64 %0, {%1,%2};" : "=l"(r) : "f"(lo), "f"(hi)); return r;
}
__device__ __forceinline__ void upk2(u64 v, float& lo, float& hi) {
    asm("mov.b64 {%0,%1}, %2;" : "=f"(lo), "=f"(hi) : "l"(v));
}
__device__ __forceinline__ void fma2(u64& d, u64 a, u64 b) {
    asm("fma.rn.f32x2 %0, %1, %2, %0;" : "+l"(d) : "l"(a), "l"(b));
}

// ---------------------------------------------------------------------------
// Kernel 1: 1-D nearest neighbor (|ci-cj| == sqrt((ci-cj)^2) exactly in RN).
// ---------------------------------------------------------------------------
#define NN_TILE 2048
__global__ __launch_bounds__(256) void nn_kernel(const float* __restrict__ c, int B) {
    __shared__ float ct[NN_TILE];
    int lane = threadIdx.x & 31;
    int w    = threadIdx.x >> 5;
    int q    = blockIdx.x * 8 + w;
    float cq = (q < B) ? c[q] : 0.f;
    float bestD = 3.0e38f; int bestJ = 0;
    for (int t0 = 0; t0 < B; t0 += NN_TILE) {
        int nt = min(NN_TILE, B - t0);
        __syncthreads();
        for (int i = threadIdx.x; i < nt; i += 256) ct[i] = c[t0 + i];
        __syncthreads();
        for (int jj = lane; jj < nt; jj += 32) {
            int j = t0 + jj;
            float d = fabsf(cq - ct[jj]);
            if (j == q) d += 1e9f;
            if (d < bestD) { bestD = d; bestJ = j; }
        }
    }
#pragma unroll
    for (int off = 16; off; off >>= 1) {
        float dO = __shfl_down_sync(0xffffffffu, bestD, off);
        int   jO = __shfl_down_sync(0xffffffffu, bestJ, off);
        if (dO < bestD || (dO == bestD && jO < bestJ)) { bestD = dO; bestJ = jO; }
    }
    if (lane == 0 && q < B) g_c0[q] = c[bestJ];
}

// ---------------------------------------------------------------------------
// 64-k tile matvec: thread owns 8 neurons (n0..n0+7, as 4 f32x2 pairs) x 4
// samples. acc[p*4+si]. Weights W[k][n] natural floats (row 64); acts A[k][.]
// dup u64 with slot(si,sG) = (si>>1)*32 + sG*2 + (si&1).
// ---------------------------------------------------------------------------
__device__ __forceinline__ void mv(const float* __restrict__ W,
                                   const u64* __restrict__ A,
                                   int n0, int sG2, u64 acc[16]) {
#pragma unroll 8
    for (int k = 0; k < 64; k++) {
        ulonglong2 wA  = *(const ulonglong2*)(W + k * 64 + n0);       // pairs 0,1
        ulonglong2 wB  = *(const ulonglong2*)(W + k * 64 + n0 + 4);   // pairs 2,3
        ulonglong2 h01 = *(const ulonglong2*)(A + k * 64 + sG2);      // dup s0,s1
        ulonglong2 h23 = *(const ulonglong2*)(A + k * 64 + 32 + sG2); // dup s2,s3
        fma2(acc[0],  wA.x, h01.x); fma2(acc[1],  wA.x, h01.y);
        fma2(acc[2],  wA.x, h23.x); fma2(acc[3],  wA.x, h23.y);
        fma2(acc[4],  wA.y, h01.x); fma2(acc[5],  wA.y, h01.y);
        fma2(acc[6],  wA.y, h23.x); fma2(acc[7],  wA.y, h23.y);
        fma2(acc[8],  wB.x, h01.x); fma2(acc[9],  wB.x, h01.y);
        fma2(acc[10], wB.x, h23.x); fma2(acc[11], wB.x, h23.y);
        fma2(acc[12], wB.y, h01.x); fma2(acc[13], wB.y, h01.y);
        fma2(acc[14], wB.y, h23.x); fma2(acc[15], wB.y, h23.y);
    }
}

// acc -> v[r][si]  (r = neuron offset 0..7)
__device__ __forceinline__ void unpack(const u64 acc[16], float v[8][4]) {
#pragma unroll
    for (int p = 0; p < 4; p++)
#pragma unroll
        for (int si = 0; si < 4; si++)
            upk2(acc[p * 4 + si], v[2 * p][si], v[2 * p + 1][si]);
}

// store v dup-pairs into ActY, phase-contiguous layout
__device__ __forceinline__ void store_dup(u64* __restrict__ Y, int n0, int sG2,
                                          const float v[8][4]) {
#pragma unroll
    for (int r = 0; r < 8; r++) {
        ulonglong2 t0, t1;
        t0.x = pk2(v[r][0], v[r][0]); t0.y = pk2(v[r][1], v[r][1]);
        t1.x = pk2(v[r][2], v[r][2]); t1.y = pk2(v[r][3], v[r][3]);
        *(ulonglong2*)(Y + (n0 + r) * 64 + sG2)      = t0;
        *(ulonglong2*)(Y + (n0 + r) * 64 + 32 + sG2) = t1;
    }
}

// ---------------------------------------------------------------------------
// Kernel 2: block = 128 threads = 64 neurons x 64 samples.
// sG = tid&15 (16 sample-groups of 4), nG = tid>>4 (8 neuron-groups of 8).
// ---------------------------------------------------------------------------
__global__ __launch_bounds__(128, 1) void solver_kernel(
    const float* __restrict__ x,
    const float* __restrict__ W1, const float* __restrict__ b1,
    const float* __restrict__ W2, const float* __restrict__ b2,
    const float* __restrict__ W3, const float* __restrict__ b3,
    const float* __restrict__ W4,
    float* __restrict__ out)
{
    extern __shared__ __align__(16) char smraw[];
    float* W2T = (float*)smraw;                 // [64][64] W2T[k][n]=W2[n][k]
    float* W3T = W2T + 4096;
    float* W2N = W3T + 4096;                    // natural
    float* W3N = W2N + 4096;
    u64*  ActA = (u64*)(W3N + 4096);            // [64][64] dup
    u64*  ActB = ActA + 4096;
    u64*  b2d  = ActB + 4096;                   // [32] f32x2 bias pairs
    u64*  b3d  = b2d + 32;
    float* red = (float*)(b3d + 32);            // [4][64]

    int tid = threadIdx.x;
    int lane = tid & 31, warp = tid >> 5;
    int sG = tid & 15, nG = tid >> 4;
    int n0 = nG * 8, sG2 = sG * 2;

    for (int i = tid; i < 1024; i += 128) {
        ((float4*)W2N)[i] = ((const float4*)W2)[i];
        ((float4*)W3N)[i] = ((const float4*)W3)[i];
    }
    __syncthreads();
    for (int i = tid; i < 4096; i += 128) {
        int n = i >> 6, k = i & 63;
        W2T[k * 64 + n] = W2N[i];
        W3T[k * 64 + n] = W3N[i];
    }
    if (tid < 32) {
        b2d[tid] = pk2(b2[2 * tid], b2[2 * tid + 1]);
        b3d[tid] = pk2(b3[2 * tid], b3[2 * tid + 1]);
    }

    int gs = blockIdx.x * 64 + sG * 4;          // this thread's 4 samples
    float xs[4], cs[4];
#pragma unroll
    for (int si = 0; si < 4; si++) { xs[si] = x[gs + si]; cs[si] = g_c0[gs + si]; }

    float a[8][4], w1y[8], w4r[8];
#pragma unroll
    for (int r = 0; r < 8; r++) {
        int n = n0 + r;
        float w1x = W1[n * 3 + 0]; w1y[r] = W1[n * 3 + 1];
        float w1c = W1[n * 3 + 2]; float bb = b1[n];
        w4r[r] = W4[n];
#pragma unroll
        for (int si = 0; si < 4; si++)
            a[r][si] = fmaf(w1x, xs[si], fmaf(w1c, cs[si], bb));
    }
    __syncthreads();

    float y[4] = {0.f, 0.f, 0.f, 0.f};          // Y_MEAN = 0

    for (int step = 0; step < NSTEPS; step++) {
        // ---- layer 1 (rank-1 in y) -> h1 ----
        unsigned m1 = 0;
        float v[8][4];
#pragma unroll
        for (int r = 0; r < 8; r++)
#pragma unroll
            for (int si = 0; si < 4; si++) {
                float z = fmaf(w1y[r], y[si], a[r][si]);
                if (z > 0.f) m1 |= 1u << (r * 4 + si);
                v[r][si] = fmaxf(z, 0.f);
            }
        store_dup(ActA, n0, sG2, v);
        __syncthreads();

        // ---- fwd2: z2 = W2 h1 + b2 ----
        u64 acc[16];
        {
            ulonglong2 ba = *(const ulonglong2*)(b2d + nG * 4);
            ulonglong2 bb = *(const ulonglong2*)(b2d + nG * 4 + 2);
#pragma unroll
            for (int si = 0; si < 4; si++) {
                acc[si] = ba.x; acc[4 + si] = ba.y;
                acc[8 + si] = bb.x; acc[12 + si] = bb.y;
            }
        }
        mv(W2T, ActA, n0, sG2, acc);
        unsigned m2 = 0;
        unpack(acc, v);
#pragma unroll
        for (int r = 0; r < 8; r++)
#pragma unroll
            for (int si = 0; si < 4; si++) {
                if (v[r][si] > 0.f) m2 |= 1u << (r * 4 + si);
                v[r][si] = fmaxf(v[r][si], 0.f);
            }
        store_dup(ActB, n0, sG2, v);
        __syncthreads();

        // ---- fwd3: z3 = W3 h2 + b3 -> g3 = (z3>0)*W4 ----
        {
            ulonglong2 ba = *(const ulonglong2*)(b3d + nG * 4);
            ulonglong2 bb = *(const ulonglong2*)(b3d + nG * 4 + 2);
#pragma unroll
            for (int si = 0; si < 4; si++) {
                acc[si] = ba.x; acc[4 + si] = ba.y;
                acc[8 + si] = bb.x; acc[12 + si] = bb.y;
            }
        }
        mv(W3T, ActB, n0, sG2, acc);
        unpack(acc, v);
#pragma unroll
        for (int r = 0; r < 8; r++)
#pragma unroll
            for (int si = 0; si < 4; si++)
                v[r][si] = (v[r][si] > 0.f) ? w4r[r] : 0.f;
        store_dup(ActA, n0, sG2, v);
        __syncthreads();

        // ---- bwd3: g2 = m2 .* (W3^T g3) ----
#pragma unroll
        for (int q = 0; q < 16; q++) acc[q] = 0;
        mv(W3N, ActA, n0, sG2, acc);
        unpack(acc, v);
#pragma unroll
        for (int r = 0; r < 8; r++)
#pragma unroll
            for (int si = 0; si < 4; si++)
                v[r][si] = (m2 & (1u << (r * 4 + si))) ? v[r][si] : 0.f;
        store_dup(ActB, n0, sG2, v);
        __syncthreads();

        // ---- bwd2: g1 = m1 .* (W2^T g2); gy = sum_n w1y[n] g1[n] ----
#pragma unroll
        for (int q = 0; q < 16; q++) acc[q] = 0;
        mv(W2N, ActB, n0, sG2, acc);
        unpack(acc, v);
        float pg[4] = {0.f, 0.f, 0.f, 0.f};
#pragma unroll
        for (int r = 0; r < 8; r++)
#pragma unroll
            for (int si = 0; si < 4; si++) {
                float g = (m1 & (1u << (r * 4 + si))) ? v[r][si] : 0.f;
                pg[si] = fmaf(w1y[r], g, pg[si]);
            }
        // combine the warp's two neuron-groups (lanes differ in bit 4)
#pragma unroll
        for (int si = 0; si < 4; si++)
            pg[si] += __shfl_xor_sync(0xffffffffu, pg[si], 16);
        if (!(lane & 16)) {
            float4 t = make_float4(pg[0], pg[1], pg[2], pg[3]);
            *(float4*)(red + warp * 64 + sG * 4) = t;
        }
        __syncthreads();
        {
            float4 r0 = *(const float4*)(red + 0 * 64 + sG * 4);
            float4 r1 = *(const float4*)(red + 1 * 64 + sG * 4);
            float4 r2 = *(const float4*)(red + 2 * 64 + sG * 4);
            float4 r3 = *(const float4*)(red + 3 * 64 + sG * 4);
            y[0] -= LRATE * ((r0.x + r1.x) + (r2.x + r3.x));
            y[1] -= LRATE * ((r0.y + r1.y) + (r2.y + r3.y));
            y[2] -= LRATE * ((r0.z + r1.z) + (r2.z + r3.z));
            y[3] -= LRATE * ((r0.w + r1.w) + (r2.w + r3.w));
        }
    }

    if (nG == 0) {
        float4 t = make_float4(y[0], y[1], y[2], y[3]);
        *(float4*)(out + gs) = t;
    }
}

// ---------------------------------------------------------------------------
// Launch
// ---------------------------------------------------------------------------
extern "C" void kernel_launch(void* const* d_in, const int* in_sizes, int n_in,
                              void* d_out, int out_size) {
    const float* x  = (const float*)d_in[0];
    const float* c  = (const float*)d_in[1];
    const float* W1 = (const float*)d_in[2];
    const float* b1 = (const float*)d_in[3];
    const float* W2 = (const float*)d_in[4];
    const float* b2 = (const float*)d_in[5];
    const float* W3 = (const float*)d_in[6];
    const float* b3 = (const float*)d_in[7];
    const float* W4 = (const float*)d_in[8];
    // d_in[9] = b4: constant offset, no effect on dE/dy
    float* out = (float*)d_out;
    int B = in_sizes[0];

    // smem: 4*4096*4 (weights) + 2*4096*8 (acts) + 64*8 (bias) + 256*4 (red)
    const int SMEM = 4 * 4096 * 4 + 2 * 4096 * 8 + 64 * 8 + 256 * 4; // 132608 B
    cudaFuncSetAttribute(solver_kernel,
                         cudaFuncAttributeMaxDynamicSharedMemorySize, SMEM);

    nn_kernel<<<(B + 7) / 8, 256>>>(c, B);
    solver_kernel<<<B / 64, 128, SMEM>>>(x, W1, b1, W2, b2, W3, b3, W4, out);
}